// round 12
// baseline (speedup 1.0000x reference)
#include <cuda_runtime.h>
#include <cuda_fp16.h>
#include <cstdint>

#define BATCH 4
#define SEQ   2048
#define DMODEL 1024
#define BS_ROWS (BATCH*SEQ)   // 8192
#define WSZ (DMODEL*DMODEL)

#define BM 256
#define BN 256
#define BKE 64                 // fp16 K elems per stage (128B rows, SW128)
#define NTHREADS 512
#define STAGE_BYTES 65536      // A 32K + B 32K
#define SMEM_TOTAL (1024 + 2*STAGE_BYTES)

// ------------------------- scratch (device globals) -------------------------
__device__ __half g_Xh[BS_ROWS*DMODEL];
__device__ __half g_Wc[4*WSZ];                       // [Wq, Wk, Wv, Wo]
__device__ __half g_QKh[2*BS_ROWS*DMODEL];           // [Q, K]
__device__ __half g_Vth[(size_t)DMODEL*BS_ROWS];
__device__ __half g_Oh[BS_ROWS*DMODEL];
__device__ __half g_Ph[(size_t)BATCH*SEQ*SEQ];
__device__ __half g_Sh[(size_t)BATCH*SEQ*SEQ];       // scores, fp16
__device__ float  g_bqk[2*DMODEL];

// ------------------------- PTX helpers -------------------------
__device__ __forceinline__ uint32_t smem_u32(const void* p) {
    uint32_t a;
    asm("{ .reg .u64 t; cvta.to.shared.u64 t, %1; cvt.u32.u64 %0, t; }" : "=r"(a) : "l"(p));
    return a;
}
__device__ __forceinline__ uint32_t swz(uint32_t o) { return o ^ ((o >> 3) & 0x70); }

__device__ __forceinline__ void cp16(uint32_t s, const void* g) {
    asm volatile("cp.async.cg.shared.global [%0], [%1], 16;" :: "r"(s), "l"(g) : "memory");
}
__device__ __forceinline__ void cp_commit() { asm volatile("cp.async.commit_group;" ::: "memory"); }
__device__ __forceinline__ void cp_wait0()  { asm volatile("cp.async.wait_group 0;" ::: "memory"); }
__device__ __forceinline__ void cp_wait1()  { asm volatile("cp.async.wait_group 1;" ::: "memory"); }

__device__ __forceinline__ void ldsm4(uint32_t* r, uint32_t addr) {
    asm volatile("ldmatrix.sync.aligned.m8n8.x4.shared.b16 {%0,%1,%2,%3}, [%4];"
                 : "=r"(r[0]), "=r"(r[1]), "=r"(r[2]), "=r"(r[3]) : "r"(addr));
}
__device__ __forceinline__ void mma_fp16(float* d, const uint32_t* a, const uint32_t* b) {
    asm volatile(
        "mma.sync.aligned.m16n8k16.row.col.f32.f16.f16.f32 "
        "{%0,%1,%2,%3}, {%4,%5,%6,%7}, {%8,%9}, {%0,%1,%2,%3};"
        : "+f"(d[0]), "+f"(d[1]), "+f"(d[2]), "+f"(d[3])
        : "r"(a[0]), "r"(a[1]), "r"(a[2]), "r"(a[3]), "r"(b[0]), "r"(b[1]));
}
__device__ __forceinline__ uint32_t pack_h2(__half a, __half b) {
    __half2 p; p.x = a; p.y = b;
    return *(uint32_t*)&p;
}

// ------------------------- GEMM (single-term fp16) -------------------------
// C = alpha * A @ B^T (+bias); A [M,K] K-major fp16 (lda), B [N,K] K-major fp16 (ldb).
// OUT: 0 fp32 -> Cf; 1 fp16 -> Ch.  BIAS_MODE: 0 none, 1 per-col(n), 2 per-row(m).
// CTA 256x256, 16 warps (4m x 4n), warp tile 64x64. 2-stage cp.async.
template<int OUT, int BIAS_MODE>
__global__ void __launch_bounds__(NTHREADS, 1)
gemm_fp16(const __half* __restrict__ A, int lda, long long sA,
          const __half* __restrict__ B, int ldb, long long sB,
          float* __restrict__ Cf, __half* __restrict__ Ch, int ldc, long long sC,
          int Kdim, float alpha, const float* __restrict__ bias, int sBias)
{
    extern __shared__ char smem_raw[];
    const uint32_t su = (smem_u32(smem_raw) + 1023u) & ~1023u;

    const int tid = threadIdx.x, lane = tid & 31, wid = tid >> 5;
    const int warp_m = wid >> 2;   // 0..3
    const int warp_n = wid & 3;    // 0..3
    const int m0 = blockIdx.y * BM, n0 = blockIdx.x * BN;
    const int z = blockIdx.z;

    A += (size_t)z * sA;
    B += (size_t)z * sB;
    if (OUT == 0) Cf += (size_t)z * sC; else Ch += (size_t)z * sC;
    if (BIAS_MODE) bias += (size_t)z * sBias;

    float acc[4][8][4];
#pragma unroll
    for (int i = 0; i < 4; i++)
#pragma unroll
        for (int j = 0; j < 8; j++)
#pragma unroll
            for (int r = 0; r < 4; r++) acc[i][j][r] = 0.f;

    auto load_stage = [&](int buf, int kt) {
        const uint32_t base = su + buf * STAGE_BYTES;
        const __half* gA = A + (size_t)m0 * lda + kt;
        const __half* gB = B + (size_t)n0 * ldb + kt;
        // A: 256 rows x 128B
#pragma unroll
        for (int i = 0; i < 4; i++) {
            int u = tid + i * NTHREADS;          // 0..2047
            int r = u >> 3, eb = (u & 7) * 16;
            cp16(base + swz((uint32_t)(r * 128 + eb)), gA + (size_t)r * lda + (eb >> 1));
        }
        // B: 256 rows x 128B
#pragma unroll
        for (int i = 0; i < 4; i++) {
            int u = tid + i * NTHREADS;
            int r = u >> 3, eb = (u & 7) * 16;
            cp16(base + 32768 + swz((uint32_t)(r * 128 + eb)), gB + (size_t)r * ldb + (eb >> 1));
        }
        cp_commit();
    };

    const int arow = warp_m * 64 + (lane & 7) + ((lane >> 3) & 1) * 8;   // + mi*16
    const int achk = (lane >> 4) * 16;
    const int brow = warp_n * 64 + (lane & 7) + ((lane >> 4) & 1) * 8;   // + nj2*16
    const int bchk = ((lane >> 3) & 1) * 16;

    auto compute = [&](int buf) {
        const uint32_t aA = su + buf * STAGE_BYTES;
        const uint32_t aB = aA + 32768;
#pragma unroll
        for (int k16 = 0; k16 < 4; k16++) {
            const uint32_t kbA = (uint32_t)(k16 * 32 + achk);
            const uint32_t kbB = (uint32_t)(k16 * 32 + bchk);
            uint32_t av[4][4];
#pragma unroll
            for (int mi = 0; mi < 4; mi++)
                ldsm4(av[mi], aA + swz((uint32_t)((arow + mi * 16) * 128) + kbA));
            uint32_t bv[8][2];
#pragma unroll
            for (int nj2 = 0; nj2 < 4; nj2++) {
                uint32_t t[4];
                ldsm4(t, aB + swz((uint32_t)((brow + nj2 * 16) * 128) + kbB));
                bv[nj2*2][0] = t[0]; bv[nj2*2][1] = t[1];
                bv[nj2*2+1][0] = t[2]; bv[nj2*2+1][1] = t[3];
            }
#pragma unroll
            for (int mi = 0; mi < 4; mi++)
#pragma unroll
                for (int nj = 0; nj < 8; nj++)
                    mma_fp16(acc[mi][nj], av[mi], bv[nj]);
        }
    };

    const int NT = Kdim / BKE;
    load_stage(0, 0);
    for (int t = 0; t < NT; t++) {
        if (t + 1 < NT) { load_stage((t + 1) & 1, (t + 1) * BKE); cp_wait1(); }
        else            { cp_wait0(); }
        __syncthreads();
        compute(t & 1);
        __syncthreads();
    }

    // ---------------- epilogue ----------------
    const int gl = lane >> 2, q = lane & 3;
#pragma unroll
    for (int mi = 0; mi < 4; mi++) {
#pragma unroll
        for (int nj = 0; nj < 8; nj++) {
            const int n = n0 + warp_n * 64 + nj * 8 + q * 2;
            float bcol0 = 0.f, bcol1 = 0.f;
            if (BIAS_MODE == 1) { bcol0 = bias[n]; bcol1 = bias[n + 1]; }
#pragma unroll
            for (int h = 0; h < 2; h++) {
                const int m = m0 + warp_m * 64 + mi * 16 + gl + h * 8;
                float v0 = acc[mi][nj][2 * h + 0] * alpha;
                float v1 = acc[mi][nj][2 * h + 1] * alpha;
                if (BIAS_MODE == 1) { v0 += bcol0; v1 += bcol1; }
                if (BIAS_MODE == 2) { float bb = bias[m]; v0 += bb; v1 += bb; }
                const size_t gidx = (size_t)m * ldc + n;
                if (OUT == 0)
                    *(float2*)(Cf + gidx) = make_float2(v0, v1);
                else
                    *(uint32_t*)(Ch + gidx) = pack_h2(__float2half(v0), __float2half(v1));
            }
        }
    }
}

// ------------------------- fp32 -> fp16 converts -------------------------
__global__ void __launch_bounds__(256)
conv_f16(const float* __restrict__ x, __half* __restrict__ h, int n4)
{
    int i = blockIdx.x * blockDim.x + threadIdx.x;
    if (i >= n4) return;
    float4 t = ((const float4*)x)[i];
    uint2 hv;
    hv.x = pack_h2(__float2half(t.x), __float2half(t.y));
    hv.y = pack_h2(__float2half(t.z), __float2half(t.w));
    ((uint2*)h)[i] = hv;
}

__global__ void __launch_bounds__(256)
conv4_f16(const float* __restrict__ w0, const float* __restrict__ w1,
          const float* __restrict__ w2, const float* __restrict__ w3,
          __half* __restrict__ dst)
{
    const int seg = blockIdx.y;
    const float* s = (seg == 0) ? w0 : (seg == 1) ? w1 : (seg == 2) ? w2 : w3;
    int i = blockIdx.x * blockDim.x + threadIdx.x;
    if (i >= WSZ / 4) return;
    float4 t = ((const float4*)s)[i];
    uint2 hv;
    hv.x = pack_h2(__float2half(t.x), __float2half(t.y));
    hv.y = pack_h2(__float2half(t.z), __float2half(t.w));
    ((uint2*)(dst + (size_t)seg * WSZ))[i] = hv;
}

// ------------------------- pack Q/K biases (capture-safe copy) -------------------------
__global__ void __launch_bounds__(256)
pack_bias(const float* __restrict__ bq, const float* __restrict__ bk,
          float* __restrict__ dst)
{
    int i = blockIdx.x * blockDim.x + threadIdx.x;
    if (i < DMODEL)          dst[i] = bq[i];
    else if (i < 2 * DMODEL) dst[i] = bk[i - DMODEL];
}

// ------------------------- softmax + intensity (fp16 scores in) -> fp16 P -------------------------
__global__ void __launch_bounds__(256)
softmax_f16(const __half* __restrict__ S, const float* __restrict__ inten,
            __half* __restrict__ P)
{
    const size_t row = blockIdx.x;
    const __half* sr = S + row * SEQ;
    const float* ir = inten + row * SEQ;
    const int tid = threadIdx.x;
    const int base = tid * 8;

    uint4 sraw = *(const uint4*)(sr + base);
    float v[8];
    {
        const uint32_t* sw = (const uint32_t*)&sraw;
#pragma unroll
        for (int i = 0; i < 4; i++) {
            __half2 hh = *(const __half2*)&sw[i];
            v[2*i]   = __half2float(hh.x);
            v[2*i+1] = __half2float(hh.y);
        }
    }
    float mx = v[0];
#pragma unroll
    for (int i = 1; i < 8; i++) mx = fmaxf(mx, v[i]);
    __shared__ float red[8];
#pragma unroll
    for (int o = 16; o > 0; o >>= 1)
        mx = fmaxf(mx, __shfl_xor_sync(0xffffffffu, mx, o));
    if ((tid & 31) == 0) red[tid >> 5] = mx;
    __syncthreads();
    mx = red[0];
#pragma unroll
    for (int i = 1; i < 8; i++) mx = fmaxf(mx, red[i]);
    __syncthreads();

    float sum = 0.f;
#pragma unroll
    for (int i = 0; i < 8; i++) {
        v[i] = expf(v[i] - mx);
        sum += v[i];
    }
#pragma unroll
    for (int o = 16; o > 0; o >>= 1)
        sum += __shfl_xor_sync(0xffffffffu, sum, o);
    if ((tid & 31) == 0) red[tid >> 5] = sum;
    __syncthreads();
    sum = 0.f;
#pragma unroll
    for (int i = 0; i < 8; i++) sum += red[i];
    const float inv = 1.f / sum;

    float w[8];
    *(float4*)&w[0] = *(const float4*)(ir + base);
    *(float4*)&w[4] = *(const float4*)(ir + base + 4);

    uint4 out;
    out.x = pack_h2(__float2half(v[0]*inv + w[0]), __float2half(v[1]*inv + w[1]));
    out.y = pack_h2(__float2half(v[2]*inv + w[2]), __float2half(v[3]*inv + w[3]));
    out.z = pack_h2(__float2half(v[4]*inv + w[4]), __float2half(v[5]*inv + w[5]));
    out.w = pack_h2(__float2half(v[6]*inv + w[6]), __float2half(v[7]*inv + w[7]));
    *(uint4*)(P + row * SEQ + base) = out;
}

// ------------------------- launch -------------------------
extern "C" void kernel_launch(void* const* d_in, const int* in_sizes, int n_in,
                              void* d_out, int out_size)
{
    const float* X  = (const float*)d_in[0];
    const float* I  = (const float*)d_in[1];
    const float* Wq = (const float*)d_in[2];
    const float* bq = (const float*)d_in[3];
    const float* Wk = (const float*)d_in[4];
    const float* bk = (const float*)d_in[5];
    const float* Wv = (const float*)d_in[6];
    const float* bv = (const float*)d_in[7];
    const float* Wo = (const float*)d_in[8];
    const float* bo = (const float*)d_in[9];
    float* out = (float*)d_out;

    __half *Xh, *Wc, *QKh, *Vth, *Oh, *Ph, *Sh;
    float *bqk;
    cudaGetSymbolAddress((void**)&Xh,  g_Xh);
    cudaGetSymbolAddress((void**)&Wc,  g_Wc);
    cudaGetSymbolAddress((void**)&QKh, g_QKh);
    cudaGetSymbolAddress((void**)&Vth, g_Vth);
    cudaGetSymbolAddress((void**)&Oh,  g_Oh);
    cudaGetSymbolAddress((void**)&Ph,  g_Ph);
    cudaGetSymbolAddress((void**)&Sh,  g_Sh);
    cudaGetSymbolAddress((void**)&bqk, g_bqk);

    cudaFuncSetAttribute(gemm_fp16<1,1>, cudaFuncAttributeMaxDynamicSharedMemorySize, SMEM_TOTAL);
    cudaFuncSetAttribute(gemm_fp16<1,2>, cudaFuncAttributeMaxDynamicSharedMemorySize, SMEM_TOTAL);
    cudaFuncSetAttribute(gemm_fp16<1,0>, cudaFuncAttributeMaxDynamicSharedMemorySize, SMEM_TOTAL);
    cudaFuncSetAttribute(gemm_fp16<0,1>, cudaFuncAttributeMaxDynamicSharedMemorySize, SMEM_TOTAL);

    const int XN4 = BS_ROWS * DMODEL / 4;
    const int WN4 = WSZ / 4;

    // 1. convert inputs; pack Q/K biases
    conv_f16<<<(XN4 + 255) / 256, 256>>>(X, Xh, XN4);
    conv4_f16<<<dim3((WN4 + 255) / 256, 4), 256>>>(Wq, Wk, Wv, Wo, Wc);
    pack_bias<<<(2 * DMODEL + 255) / 256, 256>>>(bq, bk, bqk);

    dim3 blk(NTHREADS);
    const long long QKS = (long long)BS_ROWS * DMODEL;

    // 2. Q|K = X @ {Wq,Wk}^T + {bq,bk} -> fp16, fused over z
    dim3 gQK(DMODEL / BN, BS_ROWS / BM, 2);  // (4, 32, 2)
    gemm_fp16<1,1><<<gQK, blk, SMEM_TOTAL>>>(
        Xh, DMODEL, 0, Wc, DMODEL, WSZ,
        nullptr, QKh, DMODEL, QKS, DMODEL, 1.f, bqk, DMODEL);
    // 3. V^T = Wv @ X^T + bv(row) -> fp16, Vt[d, b*S+s] ld 8192
    dim3 gV(BS_ROWS / BN, DMODEL / BM, 1);   // (32, 4)
    gemm_fp16<1,2><<<gV, blk, SMEM_TOTAL>>>(
        Wc + 2 * WSZ, DMODEL, 0, Xh, DMODEL, 0,
        nullptr, Vth, BS_ROWS, 0, DMODEL, 1.f, bv, 0);
    // 4. scores = (Q K^T)/32 -> fp16, batched
    dim3 gS(SEQ / BN, SEQ / BM, BATCH);      // (8, 8, 4)
    gemm_fp16<1,0><<<gS, blk, SMEM_TOTAL>>>(
        QKh, DMODEL, (long long)SEQ * DMODEL,
        QKh + QKS, DMODEL, (long long)SEQ * DMODEL,
        nullptr, Sh, SEQ, (long long)SEQ * SEQ,
        DMODEL, 0.03125f, nullptr, 0);
    // 5. attn = softmax + intensity -> fp16
    softmax_f16<<<BATCH * SEQ, 256>>>(Sh, I, Ph);
    // 6. O = attn @ Vt^T -> fp16, batched (B slice = column offset b*S in Vt)
    dim3 gO(DMODEL / BN, SEQ / BM, BATCH);   // (4, 8, 4)
    gemm_fp16<1,0><<<gO, blk, SMEM_TOTAL>>>(
        Ph, SEQ, (long long)SEQ * SEQ,
        Vth, BS_ROWS, (long long)SEQ,
        nullptr, Oh, DMODEL, (long long)SEQ * DMODEL,
        SEQ, 1.f, nullptr, 0);
    // 7. out = O @ Wo^T + bo -> fp32
    dim3 gP(DMODEL / BN, BS_ROWS / BM, 1);   // (4, 32)
    gemm_fp16<0,1><<<gP, blk, SMEM_TOTAL>>>(
        Oh, DMODEL, 0, Wc + 3 * WSZ, DMODEL, 0,
        out, nullptr, DMODEL, 0, DMODEL, 1.f, bo, 0);
}

// round 14
// speedup vs baseline: 2.4982x; 2.4982x over previous
#include <cuda_runtime.h>
#include <cuda_fp16.h>
#include <cstdint>

#define BATCH 4
#define SEQ   2048
#define DMODEL 1024
#define BS_ROWS (BATCH*SEQ)   // 8192
#define WSZ (DMODEL*DMODEL)

#define BM 128
#define BN 256
#define BKE 128                // fp16 K elems per stage (2 x 128B chunks)
#define NTHREADS 256
#define STAGE_BYTES 98304      // A 32K (2 chunks x 16K) + B 64K (2 chunks x 32K)
#define SMEM_TOTAL (1024 + 2*STAGE_BYTES)

// ------------------------- scratch (device globals) -------------------------
__device__ __half g_Xh[BS_ROWS*DMODEL];
__device__ __half g_Wc[4*WSZ];                       // [Wq, Wk, Wv, Wo]
__device__ __half g_QKh[2*BS_ROWS*DMODEL];           // [Q, K]
__device__ __half g_Vth[(size_t)DMODEL*BS_ROWS];
__device__ __half g_Oh[BS_ROWS*DMODEL];
__device__ __half g_Ph[(size_t)BATCH*SEQ*SEQ];
__device__ __half g_Sh[(size_t)BATCH*SEQ*SEQ];       // scores, fp16
__device__ float  g_bqk[2*DMODEL];

// ------------------------- PTX helpers -------------------------
__device__ __forceinline__ uint32_t smem_u32(const void* p) {
    uint32_t a;
    asm("{ .reg .u64 t; cvta.to.shared.u64 t, %1; cvt.u32.u64 %0, t; }" : "=r"(a) : "l"(p));
    return a;
}
__device__ __forceinline__ uint32_t swz(uint32_t o) { return o ^ ((o >> 3) & 0x70); }

__device__ __forceinline__ void cp16(uint32_t s, const void* g) {
    asm volatile("cp.async.cg.shared.global [%0], [%1], 16;" :: "r"(s), "l"(g) : "memory");
}
__device__ __forceinline__ void cp_commit() { asm volatile("cp.async.commit_group;" ::: "memory"); }
__device__ __forceinline__ void cp_wait0()  { asm volatile("cp.async.wait_group 0;" ::: "memory"); }
__device__ __forceinline__ void cp_wait1()  { asm volatile("cp.async.wait_group 1;" ::: "memory"); }

__device__ __forceinline__ void ldsm4(uint32_t* r, uint32_t addr) {
    asm volatile("ldmatrix.sync.aligned.m8n8.x4.shared.b16 {%0,%1,%2,%3}, [%4];"
                 : "=r"(r[0]), "=r"(r[1]), "=r"(r[2]), "=r"(r[3]) : "r"(addr));
}
__device__ __forceinline__ void mma_fp16(float* d, const uint32_t* a, const uint32_t* b) {
    asm volatile(
        "mma.sync.aligned.m16n8k16.row.col.f32.f16.f16.f32 "
        "{%0,%1,%2,%3}, {%4,%5,%6,%7}, {%8,%9}, {%0,%1,%2,%3};"
        : "+f"(d[0]), "+f"(d[1]), "+f"(d[2]), "+f"(d[3])
        : "r"(a[0]), "r"(a[1]), "r"(a[2]), "r"(a[3]), "r"(b[0]), "r"(b[1]));
}
__device__ __forceinline__ uint32_t pack_h2(__half a, __half b) {
    __half2 p; p.x = a; p.y = b;
    return *(uint32_t*)&p;
}

// ------------------------- GEMM tile core (single-term fp16) -------------------------
// C = alpha * A @ B^T (+bias); A [*,K] K-major (lda), B [*,K] K-major (ldb).
// OUT: 0 fp32 -> Cf; 1 fp16 -> Ch. biasMode runtime: 0 none, 1 per-col(n), 2 per-row(m).
// CTA tile 128x256, 8 warps (2m x 4n), warp tile 64x64. 2-stage x 2-chunk cp.async.
template<int OUT>
__device__ __forceinline__ void gemm_tile(
    const __half* __restrict__ A, int lda,
    const __half* __restrict__ B, int ldb,
    float* __restrict__ Cf, __half* __restrict__ Ch, int ldc,
    int Kdim, float alpha, const float* __restrict__ bias, int biasMode,
    int m0, int n0, char* smem_raw)
{
    const uint32_t su = (smem_u32(smem_raw) + 1023u) & ~1023u;
    const int tid = threadIdx.x, lane = tid & 31, wid = tid >> 5;
    const int warp_m = wid >> 2;   // 0..1
    const int warp_n = wid & 3;    // 0..3

    float acc[4][8][4];
#pragma unroll
    for (int i = 0; i < 4; i++)
#pragma unroll
        for (int j = 0; j < 8; j++)
#pragma unroll
            for (int r = 0; r < 4; r++) acc[i][j][r] = 0.f;

    auto load_stage = [&](int buf, int kt) {
        const uint32_t base = su + buf * STAGE_BYTES;
        const __half* gA = A + (size_t)m0 * lda + kt;
        const __half* gB = B + (size_t)n0 * ldb + kt;
#pragma unroll
        for (int c = 0; c < 2; c++) {
            // A chunk c: 128 rows x 128B  (chunk stride 16384)
#pragma unroll
            for (int i = 0; i < 4; i++) {
                int u = tid + i * NTHREADS;          // 0..1023
                int r = u >> 3, eb = (u & 7) * 16;
                cp16(base + c * 16384 + swz((uint32_t)(r * 128 + eb)),
                     gA + (size_t)r * lda + (eb >> 1) + c * 64);
            }
            // B chunk c: 256 rows x 128B  (chunk stride 32768)
#pragma unroll
            for (int i = 0; i < 8; i++) {
                int u = tid + i * NTHREADS;          // 0..2047
                int r = u >> 3, eb = (u & 7) * 16;
                cp16(base + 32768 + c * 32768 + swz((uint32_t)(r * 128 + eb)),
                     gB + (size_t)r * ldb + (eb >> 1) + c * 64);
            }
        }
        cp_commit();
    };

    const int arow = warp_m * 64 + (lane & 7) + ((lane >> 3) & 1) * 8;   // + mi*16
    const int achk = (lane >> 4) * 16;
    const int brow = warp_n * 64 + (lane & 7) + ((lane >> 4) & 1) * 8;   // + nj2*16
    const int bchk = ((lane >> 3) & 1) * 16;

    auto compute = [&](int buf) {
        const uint32_t sb = su + buf * STAGE_BYTES;
#pragma unroll
        for (int c = 0; c < 2; c++) {
            const uint32_t aA = sb + c * 16384;
            const uint32_t aB = sb + 32768 + c * 32768;
#pragma unroll
            for (int k16 = 0; k16 < 4; k16++) {
                const uint32_t kbA = (uint32_t)(k16 * 32 + achk);
                const uint32_t kbB = (uint32_t)(k16 * 32 + bchk);
                uint32_t av[4][4];
#pragma unroll
                for (int mi = 0; mi < 4; mi++)
                    ldsm4(av[mi], aA + swz((uint32_t)((arow + mi * 16) * 128) + kbA));
                uint32_t bv[8][2];
#pragma unroll
                for (int nj2 = 0; nj2 < 4; nj2++) {
                    uint32_t t[4];
                    ldsm4(t, aB + swz((uint32_t)((brow + nj2 * 16) * 128) + kbB));
                    bv[nj2*2][0] = t[0]; bv[nj2*2][1] = t[1];
                    bv[nj2*2+1][0] = t[2]; bv[nj2*2+1][1] = t[3];
                }
#pragma unroll
                for (int mi = 0; mi < 4; mi++)
#pragma unroll
                    for (int nj = 0; nj < 8; nj++)
                        mma_fp16(acc[mi][nj], av[mi], bv[nj]);
            }
        }
    };

    const int NT = Kdim / BKE;
    load_stage(0, 0);
    for (int t = 0; t < NT; t++) {
        if (t + 1 < NT) { load_stage((t + 1) & 1, (t + 1) * BKE); cp_wait1(); }
        else            { cp_wait0(); }
        __syncthreads();
        compute(t & 1);
        __syncthreads();
    }

    // ---------------- epilogue ----------------
    const int gl = lane >> 2, q = lane & 3;
#pragma unroll
    for (int mi = 0; mi < 4; mi++) {
#pragma unroll
        for (int nj = 0; nj < 8; nj++) {
            const int n = n0 + warp_n * 64 + nj * 8 + q * 2;
            float bcol0 = 0.f, bcol1 = 0.f;
            if (biasMode == 1) { bcol0 = bias[n]; bcol1 = bias[n + 1]; }
#pragma unroll
            for (int h = 0; h < 2; h++) {
                const int m = m0 + warp_m * 64 + mi * 16 + gl + h * 8;
                float v0 = acc[mi][nj][2 * h + 0] * alpha;
                float v1 = acc[mi][nj][2 * h + 1] * alpha;
                if (biasMode == 1) { v0 += bcol0; v1 += bcol1; }
                if (biasMode == 2) { float bb = bias[m]; v0 += bb; v1 += bb; }
                const size_t gidx = (size_t)m * ldc + n;
                if (OUT == 0)
                    *(float2*)(Cf + gidx) = make_float2(v0, v1);
                else
                    *(uint32_t*)(Ch + gidx) = pack_h2(__float2half(v0), __float2half(v1));
            }
        }
    }
}

// ------------------------- standard batched GEMM wrapper -------------------------
template<int OUT, int BIAS_MODE>
__global__ void __launch_bounds__(NTHREADS, 1)
gemm_fp16(const __half* __restrict__ A, int lda, long long sA,
          const __half* __restrict__ B, int ldb, long long sB,
          float* __restrict__ Cf, __half* __restrict__ Ch, int ldc, long long sC,
          int Kdim, float alpha, const float* __restrict__ bias, int sBias)
{
    extern __shared__ char smem_raw[];
    const int z = blockIdx.z;
    A += (size_t)z * sA;
    B += (size_t)z * sB;
    if (OUT == 0) Cf += (size_t)z * sC; else Ch += (size_t)z * sC;
    if (BIAS_MODE) bias += (size_t)z * sBias;
    gemm_tile<OUT>(A, lda, B, ldb, Cf, Ch, ldc, Kdim, alpha, bias, BIAS_MODE,
                   blockIdx.y * BM, blockIdx.x * BN, smem_raw);
}

// ------------------------- merged Q|K|V projection (768 CTAs, 1 launch) -------------------------
__global__ void __launch_bounds__(NTHREADS, 1)
gemm_qkv(const __half* __restrict__ Xh, const __half* __restrict__ Wc,
         __half* __restrict__ QKh, __half* __restrict__ Vth,
         const float* __restrict__ bqk, const float* __restrict__ bv)
{
    extern __shared__ char smem_raw[];
    const int id = blockIdx.x;
    if (id < 512) {
        // Q (z=0) / K (z=1): C[8192,1024] = X @ Wz^T + bz ; tiles 64(m) x 4(n)
        const int z  = id >> 8;
        const int r  = id & 255;
        const int by = r >> 2, bx = r & 3;
        gemm_tile<1>(Xh, DMODEL, Wc + (size_t)z * WSZ, DMODEL,
                     nullptr, QKh + (size_t)z * BS_ROWS * DMODEL, DMODEL,
                     DMODEL, 1.f, bqk + z * DMODEL, 1,
                     by * BM, bx * BN, smem_raw);
    } else {
        // V^T: C[1024,8192] = Wv @ X^T + bv(row) ; tiles 8(m) x 32(n)
        const int vid = id - 512;
        const int by = vid >> 5, bx = vid & 31;
        gemm_tile<1>(Wc + 2 * (size_t)WSZ, DMODEL, Xh, DMODEL,
                     nullptr, Vth, BS_ROWS,
                     DMODEL, 1.f, bv, 2,
                     by * BM, bx * BN, smem_raw);
    }
}

// ------------------------- fp32 -> fp16 converts -------------------------
__global__ void __launch_bounds__(256)
conv_f16(const float* __restrict__ x, __half* __restrict__ h, int n4)
{
    int i = blockIdx.x * blockDim.x + threadIdx.x;
    if (i >= n4) return;
    float4 t = ((const float4*)x)[i];
    uint2 hv;
    hv.x = pack_h2(__float2half(t.x), __float2half(t.y));
    hv.y = pack_h2(__float2half(t.z), __float2half(t.w));
    ((uint2*)h)[i] = hv;
}

__global__ void __launch_bounds__(256)
conv4_f16(const float* __restrict__ w0, const float* __restrict__ w1,
          const float* __restrict__ w2, const float* __restrict__ w3,
          __half* __restrict__ dst)
{
    const int seg = blockIdx.y;
    const float* s = (seg == 0) ? w0 : (seg == 1) ? w1 : (seg == 2) ? w2 : w3;
    int i = blockIdx.x * blockDim.x + threadIdx.x;
    if (i >= WSZ / 4) return;
    float4 t = ((const float4*)s)[i];
    uint2 hv;
    hv.x = pack_h2(__float2half(t.x), __float2half(t.y));
    hv.y = pack_h2(__float2half(t.z), __float2half(t.w));
    ((uint2*)(dst + (size_t)seg * WSZ))[i] = hv;
}

// ------------------------- pack Q/K biases -------------------------
__global__ void __launch_bounds__(256)
pack_bias(const float* __restrict__ bq, const float* __restrict__ bk,
          float* __restrict__ dst)
{
    int i = blockIdx.x * blockDim.x + threadIdx.x;
    if (i < DMODEL)          dst[i] = bq[i];
    else if (i < 2 * DMODEL) dst[i] = bk[i - DMODEL];
}

// ------------------------- softmax + intensity (fp16 scores in) -> fp16 P -------------------------
__global__ void __launch_bounds__(256)
softmax_f16(const __half* __restrict__ S, const float* __restrict__ inten,
            __half* __restrict__ P)
{
    const size_t row = blockIdx.x;
    const __half* sr = S + row * SEQ;
    const float* ir = inten + row * SEQ;
    const int tid = threadIdx.x;
    const int base = tid * 8;

    uint4 sraw = *(const uint4*)(sr + base);
    float v[8];
    {
        const uint32_t* sw = (const uint32_t*)&sraw;
#pragma unroll
        for (int i = 0; i < 4; i++) {
            __half2 hh = *(const __half2*)&sw[i];
            v[2*i]   = __half2float(hh.x);
            v[2*i+1] = __half2float(hh.y);
        }
    }
    float mx = v[0];
#pragma unroll
    for (int i = 1; i < 8; i++) mx = fmaxf(mx, v[i]);
    __shared__ float red[8];
#pragma unroll
    for (int o = 16; o > 0; o >>= 1)
        mx = fmaxf(mx, __shfl_xor_sync(0xffffffffu, mx, o));
    if ((tid & 31) == 0) red[tid >> 5] = mx;
    __syncthreads();
    mx = red[0];
#pragma unroll
    for (int i = 1; i < 8; i++) mx = fmaxf(mx, red[i]);
    __syncthreads();

    float sum = 0.f;
#pragma unroll
    for (int i = 0; i < 8; i++) {
        v[i] = expf(v[i] - mx);
        sum += v[i];
    }
#pragma unroll
    for (int o = 16; o > 0; o >>= 1)
        sum += __shfl_xor_sync(0xffffffffu, sum, o);
    if ((tid & 31) == 0) red[tid >> 5] = sum;
    __syncthreads();
    sum = 0.f;
#pragma unroll
    for (int i = 0; i < 8; i++) sum += red[i];
    const float inv = 1.f / sum;

    float w[8];
    *(float4*)&w[0] = *(const float4*)(ir + base);
    *(float4*)&w[4] = *(const float4*)(ir + base + 4);

    uint4 out;
    out.x = pack_h2(__float2half(v[0]*inv + w[0]), __float2half(v[1]*inv + w[1]));
    out.y = pack_h2(__float2half(v[2]*inv + w[2]), __float2half(v[3]*inv + w[3]));
    out.z = pack_h2(__float2half(v[4]*inv + w[4]), __float2half(v[5]*inv + w[5]));
    out.w = pack_h2(__float2half(v[6]*inv + w[6]), __float2half(v[7]*inv + w[7]));
    *(uint4*)(P + row * SEQ + base) = out;
}

// ------------------------- launch -------------------------
extern "C" void kernel_launch(void* const* d_in, const int* in_sizes, int n_in,
                              void* d_out, int out_size)
{
    const float* X  = (const float*)d_in[0];
    const float* I  = (const float*)d_in[1];
    const float* Wq = (const float*)d_in[2];
    const float* bq = (const float*)d_in[3];
    const float* Wk = (const float*)d_in[4];
    const float* bk = (const float*)d_in[5];
    const float* Wv = (const float*)d_in[6];
    const float* bv = (const float*)d_in[7];
    const float* Wo = (const float*)d_in[8];
    const float* bo = (const float*)d_in[9];
    float* out = (float*)d_out;

    __half *Xh, *Wc, *QKh, *Vth, *Oh, *Ph, *Sh;
    float *bqk;
    cudaGetSymbolAddress((void**)&Xh,  g_Xh);
    cudaGetSymbolAddress((void**)&Wc,  g_Wc);
    cudaGetSymbolAddress((void**)&QKh, g_QKh);
    cudaGetSymbolAddress((void**)&Vth, g_Vth);
    cudaGetSymbolAddress((void**)&Oh,  g_Oh);
    cudaGetSymbolAddress((void**)&Ph,  g_Ph);
    cudaGetSymbolAddress((void**)&Sh,  g_Sh);
    cudaGetSymbolAddress((void**)&bqk, g_bqk);

    cudaFuncSetAttribute(gemm_qkv,       cudaFuncAttributeMaxDynamicSharedMemorySize, SMEM_TOTAL);
    cudaFuncSetAttribute(gemm_fp16<1,0>, cudaFuncAttributeMaxDynamicSharedMemorySize, SMEM_TOTAL);
    cudaFuncSetAttribute(gemm_fp16<0,1>, cudaFuncAttributeMaxDynamicSharedMemorySize, SMEM_TOTAL);

    const int XN4 = BS_ROWS * DMODEL / 4;
    const int WN4 = WSZ / 4;

    // 1. convert inputs; pack Q/K biases
    conv_f16<<<(XN4 + 255) / 256, 256>>>(X, Xh, XN4);
    conv4_f16<<<dim3((WN4 + 255) / 256, 4), 256>>>(Wq, Wk, Wv, Wo, Wc);
    pack_bias<<<(2 * DMODEL + 255) / 256, 256>>>(bq, bk, bqk);

    dim3 blk(NTHREADS);

    // 2. Q|K|V projections in one launch (512 QK tiles + 256 V tiles)
    gemm_qkv<<<768, blk, SMEM_TOTAL>>>(Xh, Wc, QKh, Vth, bqk, bv);
    // 3. scores = (Q K^T)/32 -> fp16, batched
    dim3 gS(SEQ / BN, SEQ / BM, BATCH);      // (8, 16, 4)
    gemm_fp16<1,0><<<gS, blk, SMEM_TOTAL>>>(
        QKh, DMODEL, (long long)SEQ * DMODEL,
        QKh + (size_t)BS_ROWS * DMODEL, DMODEL, (long long)SEQ * DMODEL,
        nullptr, Sh, SEQ, (long long)SEQ * SEQ,
        DMODEL, 0.03125f, nullptr, 0);
    // 4. attn = softmax + intensity -> fp16
    softmax_f16<<<BATCH * SEQ, 256>>>(Sh, I, Ph);
    // 5. O = attn @ Vt^T -> fp16, batched (B slice = column offset b*S in Vt)
    dim3 gO(DMODEL / BN, SEQ / BM, BATCH);   // (4, 16, 4)
    gemm_fp16<1,0><<<gO, blk, SMEM_TOTAL>>>(
        Ph, SEQ, (long long)SEQ * SEQ,
        Vth, BS_ROWS, (long long)SEQ,
        nullptr, Oh, DMODEL, (long long)SEQ * DMODEL,
        SEQ, 1.f, nullptr, 0);
    // 6. out = O @ Wo^T + bo -> fp32
    dim3 gP(DMODEL / BN, BS_ROWS / BM, 1);   // (4, 64)
    gemm_fp16<0,1><<<gP, blk, SMEM_TOTAL>>>(
        Oh, DMODEL, 0, Wc + 3 * WSZ, DMODEL, 0,
        out, nullptr, DMODEL, 0, DMODEL, 1.f, bo, 0);
}

// round 15
// speedup vs baseline: 2.4984x; 1.0001x over previous
#include <cuda_runtime.h>
#include <cuda_fp16.h>
#include <cstdint>

#define BATCH 4
#define SEQ   2048
#define DMODEL 1024
#define BS_ROWS (BATCH*SEQ)   // 8192
#define WSZ (DMODEL*DMODEL)

#define BM 128
#define BN 256
#define BKE 128                // fp16 K elems per stage (2 x 128B chunks)
#define NTHREADS 256
#define STAGE_BYTES 98304      // A 32K (2x16K) + B 64K (2x32K)
#define SMEM_TOTAL (1024 + 2*STAGE_BYTES)

// ------------------------- scratch (device globals) -------------------------
__device__ __half g_Xh[BS_ROWS*DMODEL];
__device__ __half g_Wc[4*WSZ];                       // [Wq, Wk, Wv, Wo]
__device__ __half g_QKVh[3*(size_t)BS_ROWS*DMODEL];  // [Q, K, V] row-major
__device__ __half g_WpT[(size_t)DMODEL*BS_ROWS];     // (V @ Wo^T)^T = Wo @ V^T
__device__ __half g_Ph[(size_t)BATCH*SEQ*SEQ];
__device__ __half g_Sh[(size_t)BATCH*SEQ*SEQ];       // scores, fp16
__device__ float  g_bqkv[3*DMODEL];

// ------------------------- PTX helpers -------------------------
__device__ __forceinline__ uint32_t smem_u32(const void* p) {
    uint32_t a;
    asm("{ .reg .u64 t; cvta.to.shared.u64 t, %1; cvt.u32.u64 %0, t; }" : "=r"(a) : "l"(p));
    return a;
}
__device__ __forceinline__ uint32_t swz(uint32_t o) { return o ^ ((o >> 3) & 0x70); }

__device__ __forceinline__ void cp16(uint32_t s, const void* g) {
    asm volatile("cp.async.cg.shared.global [%0], [%1], 16;" :: "r"(s), "l"(g) : "memory");
}
__device__ __forceinline__ void cp_commit() { asm volatile("cp.async.commit_group;" ::: "memory"); }
__device__ __forceinline__ void cp_wait0()  { asm volatile("cp.async.wait_group 0;" ::: "memory"); }
__device__ __forceinline__ void cp_wait1()  { asm volatile("cp.async.wait_group 1;" ::: "memory"); }

__device__ __forceinline__ void ldsm4(uint32_t* r, uint32_t addr) {
    asm volatile("ldmatrix.sync.aligned.m8n8.x4.shared.b16 {%0,%1,%2,%3}, [%4];"
                 : "=r"(r[0]), "=r"(r[1]), "=r"(r[2]), "=r"(r[3]) : "r"(addr));
}
__device__ __forceinline__ void mma_fp16(float* d, const uint32_t* a, const uint32_t* b) {
    asm volatile(
        "mma.sync.aligned.m16n8k16.row.col.f32.f16.f16.f32 "
        "{%0,%1,%2,%3}, {%4,%5,%6,%7}, {%8,%9}, {%0,%1,%2,%3};"
        : "+f"(d[0]), "+f"(d[1]), "+f"(d[2]), "+f"(d[3])
        : "r"(a[0]), "r"(a[1]), "r"(a[2]), "r"(a[3]), "r"(b[0]), "r"(b[1]));
}
__device__ __forceinline__ uint32_t pack_h2(__half a, __half b) {
    __half2 p; p.x = a; p.y = b;
    return *(uint32_t*)&p;
}

// ------------------------- GEMM tile core (single-term fp16) -------------------------
// C = alpha * A @ B^T (+bias); A [*,K] K-major (lda), B [*,K] K-major (ldb).
// OUT: 0 fp32 -> Cf; 1 fp16 -> Ch. biasMode runtime: 0 none, 1 per-col(n), 2 per-row(m).
// CTA tile 128x256, 8 warps (2m x 4n), warp tile 64x64. 2-stage x 2-chunk cp.async.
template<int OUT>
__device__ __forceinline__ void gemm_tile(
    const __half* __restrict__ A, int lda,
    const __half* __restrict__ B, int ldb,
    float* __restrict__ Cf, __half* __restrict__ Ch, int ldc,
    int Kdim, float alpha, const float* __restrict__ bias, int biasMode,
    int m0, int n0, char* smem_raw)
{
    const uint32_t su = (smem_u32(smem_raw) + 1023u) & ~1023u;
    const int tid = threadIdx.x, lane = tid & 31, wid = tid >> 5;
    const int warp_m = wid >> 2;   // 0..1
    const int warp_n = wid & 3;    // 0..3

    float acc[4][8][4];
#pragma unroll
    for (int i = 0; i < 4; i++)
#pragma unroll
        for (int j = 0; j < 8; j++)
#pragma unroll
            for (int r = 0; r < 4; r++) acc[i][j][r] = 0.f;

    auto load_stage = [&](int buf, int kt) {
        const uint32_t base = su + buf * STAGE_BYTES;
        const __half* gA = A + (size_t)m0 * lda + kt;
        const __half* gB = B + (size_t)n0 * ldb + kt;
#pragma unroll
        for (int c = 0; c < 2; c++) {
            // A chunk c: 128 rows x 128B  (chunk stride 16384)
#pragma unroll
            for (int i = 0; i < 4; i++) {
                int u = tid + i * NTHREADS;
                int r = u >> 3, eb = (u & 7) * 16;
                cp16(base + c * 16384 + swz((uint32_t)(r * 128 + eb)),
                     gA + (size_t)r * lda + (eb >> 1) + c * 64);
            }
            // B chunk c: 256 rows x 128B  (chunk stride 32768)
#pragma unroll
            for (int i = 0; i < 8; i++) {
                int u = tid + i * NTHREADS;
                int r = u >> 3, eb = (u & 7) * 16;
                cp16(base + 32768 + c * 32768 + swz((uint32_t)(r * 128 + eb)),
                     gB + (size_t)r * ldb + (eb >> 1) + c * 64);
            }
        }
        cp_commit();
    };

    const int arow = warp_m * 64 + (lane & 7) + ((lane >> 3) & 1) * 8;   // + mi*16
    const int achk = (lane >> 4) * 16;
    const int brow = warp_n * 64 + (lane & 7) + ((lane >> 4) & 1) * 8;   // + nj2*16
    const int bchk = ((lane >> 3) & 1) * 16;

    auto compute = [&](int buf) {
        const uint32_t sb = su + buf * STAGE_BYTES;
#pragma unroll
        for (int c = 0; c < 2; c++) {
            const uint32_t aA = sb + c * 16384;
            const uint32_t aB = sb + 32768 + c * 32768;
#pragma unroll
            for (int k16 = 0; k16 < 4; k16++) {
                const uint32_t kbA = (uint32_t)(k16 * 32 + achk);
                const uint32_t kbB = (uint32_t)(k16 * 32 + bchk);
                uint32_t av[4][4];
#pragma unroll
                for (int mi = 0; mi < 4; mi++)
                    ldsm4(av[mi], aA + swz((uint32_t)((arow + mi * 16) * 128) + kbA));
                uint32_t bv[8][2];
#pragma unroll
                for (int nj2 = 0; nj2 < 4; nj2++) {
                    uint32_t t[4];
                    ldsm4(t, aB + swz((uint32_t)((brow + nj2 * 16) * 128) + kbB));
                    bv[nj2*2][0] = t[0]; bv[nj2*2][1] = t[1];
                    bv[nj2*2+1][0] = t[2]; bv[nj2*2+1][1] = t[3];
                }
#pragma unroll
                for (int mi = 0; mi < 4; mi++)
#pragma unroll
                    for (int nj = 0; nj < 8; nj++)
                        mma_fp16(acc[mi][nj], av[mi], bv[nj]);
            }
        }
    };

    const int NT = Kdim / BKE;
    load_stage(0, 0);
    for (int t = 0; t < NT; t++) {
        if (t + 1 < NT) { load_stage((t + 1) & 1, (t + 1) * BKE); cp_wait1(); }
        else            { cp_wait0(); }
        __syncthreads();
        compute(t & 1);
        __syncthreads();
    }

    // ---------------- epilogue ----------------
    const int gl = lane >> 2, q = lane & 3;
#pragma unroll
    for (int mi = 0; mi < 4; mi++) {
#pragma unroll
        for (int nj = 0; nj < 8; nj++) {
            const int n = n0 + warp_n * 64 + nj * 8 + q * 2;
            float bcol0 = 0.f, bcol1 = 0.f;
            if (biasMode == 1) { bcol0 = bias[n]; bcol1 = bias[n + 1]; }
#pragma unroll
            for (int h = 0; h < 2; h++) {
                const int m = m0 + warp_m * 64 + mi * 16 + gl + h * 8;
                float v0 = acc[mi][nj][2 * h + 0] * alpha;
                float v1 = acc[mi][nj][2 * h + 1] * alpha;
                if (biasMode == 1) { v0 += bcol0; v1 += bcol1; }
                if (biasMode == 2) { float bb = bias[m]; v0 += bb; v1 += bb; }
                const size_t gidx = (size_t)m * ldc + n;
                if (OUT == 0)
                    *(float2*)(Cf + gidx) = make_float2(v0, v1);
                else
                    *(uint32_t*)(Ch + gidx) = pack_h2(__float2half(v0), __float2half(v1));
            }
        }
    }
}

// ------------------------- standard batched GEMM wrapper -------------------------
template<int OUT, int BIAS_MODE>
__global__ void __launch_bounds__(NTHREADS, 1)
gemm_fp16(const __half* __restrict__ A, int lda, long long sA,
          const __half* __restrict__ B, int ldb, long long sB,
          float* __restrict__ Cf, __half* __restrict__ Ch, int ldc, long long sC,
          int Kdim, float alpha, const float* __restrict__ bias, int sBias)
{
    extern __shared__ char smem_raw[];
    const int z = blockIdx.z;
    A += (size_t)z * sA;
    B += (size_t)z * sB;
    if (OUT == 0) Cf += (size_t)z * sC; else Ch += (size_t)z * sC;
    if (BIAS_MODE) bias += (size_t)z * sBias;
    gemm_tile<OUT>(A, lda, B, ldb, Cf, Ch, ldc, Kdim, alpha, bias, BIAS_MODE,
                   blockIdx.y * BM, blockIdx.x * BN, smem_raw);
}

// ------------------------- merged Q|K|V projections (768 CTAs) -------------------------
// z-th projection: C[8192,1024] = X @ Wz^T + bz, row-major fp16.
__global__ void __launch_bounds__(NTHREADS, 1)
gemm_qkv(const __half* __restrict__ Xh, const __half* __restrict__ Wc,
         __half* __restrict__ QKVh, const float* __restrict__ bqkv)
{
    extern __shared__ char smem_raw[];
    const int id = blockIdx.x;
    const int z  = id >> 8;          // 0=Q, 1=K, 2=V
    const int r  = id & 255;
    const int by = r >> 2, bx = r & 3;   // 64 m-tiles? no: 8192/128=64... r: 256 = 64m x 4n
    gemm_tile<1>(Xh, DMODEL, Wc + (size_t)z * WSZ, DMODEL,
                 nullptr, QKVh + (size_t)z * BS_ROWS * DMODEL, DMODEL,
                 DMODEL, 1.f, bqkv + z * DMODEL, 1,
                 (r >> 2) * BM, (r & 3) * BN, smem_raw);
    (void)by; (void)bx;
}

// ------------------------- merged scores | W'^T (768 CTAs) -------------------------
// id<512: scores_z = (Q_z K_z^T)/32 -> fp16  (z=id>>7; 16m x 8n tiles)
// id>=512: W'^T = Wo @ V^T -> fp16 [D, B*S]  (8m x 32n tiles)
__global__ void __launch_bounds__(NTHREADS, 1)
gemm_sw(const __half* __restrict__ QKVh, const __half* __restrict__ Wo,
        __half* __restrict__ Sh, __half* __restrict__ WpT)
{
    extern __shared__ char smem_raw[];
    const int id = blockIdx.x;
    const size_t PS = (size_t)BS_ROWS * DMODEL;
    if (id < 512) {
        const int z = id >> 7;           // batch 0..3
        const int r = id & 127;          // 128 = 16m x 8n
        const int by = r >> 3, bx = r & 7;
        const __half* Qz = QKVh + (size_t)z * SEQ * DMODEL;
        const __half* Kz = QKVh + PS + (size_t)z * SEQ * DMODEL;
        gemm_tile<1>(Qz, DMODEL, Kz, DMODEL,
                     nullptr, Sh + (size_t)z * SEQ * SEQ, SEQ,
                     DMODEL, 0.03125f, nullptr, 0,
                     by * BM, bx * BN, smem_raw);
    } else {
        const int vid = id - 512;        // 256 = 8m x 32n
        const int by = vid >> 5, bx = vid & 31;
        gemm_tile<1>(Wo, DMODEL, QKVh + 2 * PS, DMODEL,
                     nullptr, WpT, BS_ROWS,
                     DMODEL, 1.f, nullptr, 0,
                     by * BM, bx * BN, smem_raw);
    }
}

// ------------------------- fp32 -> fp16 converts -------------------------
__global__ void __launch_bounds__(256)
conv_f16(const float* __restrict__ x, __half* __restrict__ h, int n4)
{
    int i = blockIdx.x * blockDim.x + threadIdx.x;
    if (i >= n4) return;
    float4 t = ((const float4*)x)[i];
    uint2 hv;
    hv.x = pack_h2(__float2half(t.x), __float2half(t.y));
    hv.y = pack_h2(__float2half(t.z), __float2half(t.w));
    ((uint2*)h)[i] = hv;
}

__global__ void __launch_bounds__(256)
conv4_f16(const float* __restrict__ w0, const float* __restrict__ w1,
          const float* __restrict__ w2, const float* __restrict__ w3,
          __half* __restrict__ dst)
{
    const int seg = blockIdx.y;
    const float* s = (seg == 0) ? w0 : (seg == 1) ? w1 : (seg == 2) ? w2 : w3;
    int i = blockIdx.x * blockDim.x + threadIdx.x;
    if (i >= WSZ / 4) return;
    float4 t = ((const float4*)s)[i];
    uint2 hv;
    hv.x = pack_h2(__float2half(t.x), __float2half(t.y));
    hv.y = pack_h2(__float2half(t.z), __float2half(t.w));
    ((uint2*)(dst + (size_t)seg * WSZ))[i] = hv;
}

// ------------------------- pack Q/K/V biases -------------------------
__global__ void __launch_bounds__(256)
pack_bias(const float* __restrict__ bq, const float* __restrict__ bk,
          const float* __restrict__ bv, float* __restrict__ dst)
{
    int i = blockIdx.x * blockDim.x + threadIdx.x;
    if (i < DMODEL)               dst[i] = bq[i];
    else if (i < 2 * DMODEL)      dst[i] = bk[i - DMODEL];
    else if (i < 3 * DMODEL)      dst[i] = bv[i - 2 * DMODEL];
}

// ------------------------- softmax + intensity (fp16 scores in) -> fp16 P -------------------------
__global__ void __launch_bounds__(256)
softmax_f16(const __half* __restrict__ S, const float* __restrict__ inten,
            __half* __restrict__ P)
{
    const size_t row = blockIdx.x;
    const __half* sr = S + row * SEQ;
    const float* ir = inten + row * SEQ;
    const int tid = threadIdx.x;
    const int base = tid * 8;

    uint4 sraw = *(const uint4*)(sr + base);
    float v[8];
    {
        const uint32_t* sw = (const uint32_t*)&sraw;
#pragma unroll
        for (int i = 0; i < 4; i++) {
            __half2 hh = *(const __half2*)&sw[i];
            v[2*i]   = __half2float(hh.x);
            v[2*i+1] = __half2float(hh.y);
        }
    }
    float mx = v[0];
#pragma unroll
    for (int i = 1; i < 8; i++) mx = fmaxf(mx, v[i]);
    __shared__ float red[8];
#pragma unroll
    for (int o = 16; o > 0; o >>= 1)
        mx = fmaxf(mx, __shfl_xor_sync(0xffffffffu, mx, o));
    if ((tid & 31) == 0) red[tid >> 5] = mx;
    __syncthreads();
    mx = red[0];
#pragma unroll
    for (int i = 1; i < 8; i++) mx = fmaxf(mx, red[i]);
    __syncthreads();

    float sum = 0.f;
#pragma unroll
    for (int i = 0; i < 8; i++) {
        v[i] = expf(v[i] - mx);
        sum += v[i];
    }
#pragma unroll
    for (int o = 16; o > 0; o >>= 1)
        sum += __shfl_xor_sync(0xffffffffu, sum, o);
    if ((tid & 31) == 0) red[tid >> 5] = sum;
    __syncthreads();
    sum = 0.f;
#pragma unroll
    for (int i = 0; i < 8; i++) sum += red[i];
    const float inv = 1.f / sum;

    float w[8];
    *(float4*)&w[0] = *(const float4*)(ir + base);
    *(float4*)&w[4] = *(const float4*)(ir + base + 4);

    uint4 out;
    out.x = pack_h2(__float2half(v[0]*inv + w[0]), __float2half(v[1]*inv + w[1]));
    out.y = pack_h2(__float2half(v[2]*inv + w[2]), __float2half(v[3]*inv + w[3]));
    out.z = pack_h2(__float2half(v[4]*inv + w[4]), __float2half(v[5]*inv + w[5]));
    out.w = pack_h2(__float2half(v[6]*inv + w[6]), __float2half(v[7]*inv + w[7]));
    *(uint4*)(P + row * SEQ + base) = out;
}

// ------------------------- launch -------------------------
extern "C" void kernel_launch(void* const* d_in, const int* in_sizes, int n_in,
                              void* d_out, int out_size)
{
    const float* X  = (const float*)d_in[0];
    const float* I  = (const float*)d_in[1];
    const float* Wq = (const float*)d_in[2];
    const float* bq = (const float*)d_in[3];
    const float* Wk = (const float*)d_in[4];
    const float* bk = (const float*)d_in[5];
    const float* Wv = (const float*)d_in[6];
    const float* bv = (const float*)d_in[7];
    const float* Wo = (const float*)d_in[8];
    const float* bo = (const float*)d_in[9];
    float* out = (float*)d_out;

    __half *Xh, *Wc, *QKVh, *WpT, *Ph, *Sh;
    float *bqkv;
    cudaGetSymbolAddress((void**)&Xh,   g_Xh);
    cudaGetSymbolAddress((void**)&Wc,   g_Wc);
    cudaGetSymbolAddress((void**)&QKVh, g_QKVh);
    cudaGetSymbolAddress((void**)&WpT,  g_WpT);
    cudaGetSymbolAddress((void**)&Ph,   g_Ph);
    cudaGetSymbolAddress((void**)&Sh,   g_Sh);
    cudaGetSymbolAddress((void**)&bqkv, g_bqkv);

    cudaFuncSetAttribute(gemm_qkv,       cudaFuncAttributeMaxDynamicSharedMemorySize, SMEM_TOTAL);
    cudaFuncSetAttribute(gemm_sw,        cudaFuncAttributeMaxDynamicSharedMemorySize, SMEM_TOTAL);
    cudaFuncSetAttribute(gemm_fp16<0,1>, cudaFuncAttributeMaxDynamicSharedMemorySize, SMEM_TOTAL);

    const int XN4 = BS_ROWS * DMODEL / 4;
    const int WN4 = WSZ / 4;

    // 1. convert inputs; pack Q/K/V biases
    conv_f16<<<(XN4 + 255) / 256, 256>>>(X, Xh, XN4);
    conv4_f16<<<dim3((WN4 + 255) / 256, 4), 256>>>(Wq, Wk, Wv, Wo, Wc);
    pack_bias<<<(3 * DMODEL + 255) / 256, 256>>>(bq, bk, bv, bqkv);

    dim3 blk(NTHREADS);

    // 2. Q|K|V projections in one 768-CTA launch
    gemm_qkv<<<768, blk, SMEM_TOTAL>>>(Xh, Wc, QKVh, bqkv);
    // 3. scores (512 tiles) | W'^T = Wo @ V^T (256 tiles) in one 768-CTA launch
    gemm_sw<<<768, blk, SMEM_TOTAL>>>(QKVh, Wc + 3 * (size_t)WSZ, Sh, WpT);
    // 4. attn = softmax + intensity -> fp16
    softmax_f16<<<BATCH * SEQ, 256>>>(Sh, I, Ph);
    // 5. out = P @ W' + bo -> fp32, batched (B slice = column offset z*S in WpT)
    dim3 gO(DMODEL / BN, SEQ / BM, BATCH);   // (4, 16, 4)
    gemm_fp16<0,1><<<gO, blk, SMEM_TOTAL>>>(
        Ph, SEQ, (long long)SEQ * SEQ,
        WpT, BS_ROWS, (long long)SEQ,
        out, nullptr, DMODEL, (long long)SEQ * DMODEL,
        SEQ, 1.f, bo, 0);
}